// round 14
// baseline (speedup 1.0000x reference)
#include <cuda_runtime.h>
#include <cuda_bf16.h>
#include <cstdint>

#define NTOK 49
#define DIMC 256
#define NH   8
#define HD   32
#define ATT_SCALE 0.17677669529663687f   // 32^-0.5

#define TOKENS   100352                  // 2048 * 49
#define NTILES   784                     // TOKENS / 128
#define QKV_NC   24                      // 768 / 32
#define PROJ_NC  8                       // 256 / 32
#define CH_ELEMS 10240                   // 256 rows * 40 (32 data + 8 pad) bf16
#define CH_BYTES 20480
#define NWMAX    64
#define BMF_PER_WH 3584                  // 4mf * 7nf * 4j * 32lane

// ---------------- global scratch (static, no allocs) ----------------
__device__ __align__(128) float g_qkv[(size_t)TOKENS * 768];
__device__ __align__(128) float g_attn[(size_t)TOKENS * 256];
__device__ __align__(128) float g_bm[(size_t)NWMAX * NH * BMF_PER_WH];
__device__ __align__(128) __nv_bfloat16 g_wq_hi[QKV_NC * CH_ELEMS];
__device__ __align__(128) __nv_bfloat16 g_wq_lo[QKV_NC * CH_ELEMS];
__device__ __align__(128) __nv_bfloat16 g_wp_hi[PROJ_NC * CH_ELEMS];
__device__ __align__(128) __nv_bfloat16 g_wp_lo[PROJ_NC * CH_ELEMS];

// ---------------- ptx helpers ----------------
__device__ __forceinline__ uint32_t smem_u32(const void* p) {
    uint32_t a;
    asm("{ .reg .u64 t; cvta.to.shared.u64 t, %1; cvt.u32.u64 %0, t; }"
        : "=r"(a) : "l"(p));
    return a;
}

#define MBAR_INIT(a, c) \
    asm volatile("mbarrier.init.shared.b64 [%0], %1;" :: "r"(a), "r"(c) : "memory")
#define MBAR_EXPECT_TX(a, b) \
    asm volatile("mbarrier.arrive.expect_tx.shared.b64 _, [%0], %1;" :: "r"(a), "r"(b) : "memory")
#define MBAR_WAIT(a, ph) do { \
    uint32_t _m = (a); uint32_t _p = (ph); uint32_t _d; \
    asm volatile("{\n\t.reg .pred p;\n\t" \
        "mbarrier.try_wait.parity.acquire.cta.shared::cta.b64 p, [%1], %2;\n\t" \
        "selp.b32 %0, 1, 0, p;\n\t}" : "=r"(_d) : "r"(_m), "r"(_p) : "memory"); \
    if (!_d) { \
        asm volatile("{\n\t.reg .pred P1;\n\tWL_%=:\n\t" \
            "mbarrier.try_wait.parity.acquire.cta.shared::cta.b64 P1, [%0], %1, 0x989680;\n\t" \
            "@P1 bra.uni WD_%=;\n\tbra.uni WL_%=;\n\tWD_%=:\n\t}" \
            :: "r"(_m), "r"(_p) : "memory"); \
    } } while (0)

#define BULK_G2S(dst, src, bytes, mbar) \
    asm volatile("cp.async.bulk.shared::cluster.global.mbarrier::complete_tx::bytes " \
                 "[%0], [%1], %2, [%3];" \
                 :: "r"(dst), "l"(src), "r"(bytes), "r"(mbar) : "memory")

#define LDSM_X4(r, addr) \
    asm volatile("ldmatrix.sync.aligned.m8n8.x4.shared.b16 {%0,%1,%2,%3}, [%4];" \
        : "=r"((r)[0]), "=r"((r)[1]), "=r"((r)[2]), "=r"((r)[3]) : "r"(addr))

#define LDSM_X2T(r, addr) \
    asm volatile("ldmatrix.sync.aligned.m8n8.x2.trans.shared.b16 {%0,%1}, [%2];" \
        : "=r"((r)[0]), "=r"((r)[1]) : "r"(addr))

#define MMA16816(c, a, b) \
    asm volatile("mma.sync.aligned.m16n8k16.row.col.f32.bf16.bf16.f32 " \
        "{%0,%1,%2,%3}, {%4,%5,%6,%7}, {%8,%9}, {%0,%1,%2,%3};" \
        : "+f"((c)[0]), "+f"((c)[1]), "+f"((c)[2]), "+f"((c)[3]) \
        : "r"((a)[0]), "r"((a)[1]), "r"((a)[2]), "r"((a)[3]), \
          "r"((b)[0]), "r"((b)[1]))

// split x,y to bf16 hi/lo packed pairs (x in low half)
__device__ __forceinline__ void sp2(float x, float y, uint32_t& h, uint32_t& l) {
    __nv_bfloat16 hx = __float2bfloat16(x), hy = __float2bfloat16(y);
    __nv_bfloat16 lx = __float2bfloat16(x - __bfloat162float(hx));
    __nv_bfloat16 ly = __float2bfloat16(y - __bfloat162float(hy));
    h = ((uint32_t)__bfloat16_as_ushort(hy) << 16) | __bfloat16_as_ushort(hx);
    l = ((uint32_t)__bfloat16_as_ushort(ly) << 16) | __bfloat16_as_ushort(lx);
}

// ---------------- kernel 1: weight prep + fragment-ordered bias/mask ---------
__global__ void prep_weights(const float* __restrict__ qkv_w,
                             const float* __restrict__ proj_w,
                             const float* __restrict__ mask,
                             const float* __restrict__ bias_table,
                             const int*   __restrict__ rel_index,
                             int nW) {
    int c = blockIdx.x;
    if (c < QKV_NC + PROJ_NC) {
        bool isq = c < QKV_NC;
        int chunk = isq ? c : c - QKV_NC;
        const float* W = isq ? qkv_w : proj_w;
        int ncols = isq ? 768 : 256;
        __nv_bfloat16* hi = (isq ? g_wq_hi : g_wp_hi) + chunk * CH_ELEMS;
        __nv_bfloat16* lo = (isq ? g_wq_lo : g_wp_lo) + chunk * CH_ELEMS;
        for (int idx = threadIdx.x; idx < CH_ELEMS; idx += blockDim.x) {
            int k = idx / 40;
            int n = idx - k * 40;
            float w = (n < 32) ? __ldg(W + k * ncols + chunk * 32 + n) : 0.0f;
            __nv_bfloat16 h = __float2bfloat16(w);
            __nv_bfloat16 l = __float2bfloat16(w - __bfloat162float(h));
            hi[idx] = h;
            lo[idx] = l;
        }
    } else {
        // fragment-ordered: g_bm[wh][((mf*7+nf)*4+j)*32+lane]
        int total = nW * NH * BMF_PER_WH;
        int nb = gridDim.x - (QKV_NC + PROJ_NC);
        for (int idx = (c - QKV_NC - PROJ_NC) * blockDim.x + threadIdx.x;
             idx < total; idx += nb * blockDim.x) {
            int wh  = idx / BMF_PER_WH;
            int rem = idx - wh * BMF_PER_WH;
            int lane = rem & 31;
            int t = rem >> 5;
            int j = t & 3;
            int mfnf = t >> 2;
            int nf = mfnf % 7, mf = mfnf / 7;
            int row = mf * 16 + (lane >> 2) + ((j >> 1) << 3);
            int col = nf * 8 + 2 * (lane & 3) + (j & 1);
            int w = wh >> 3, h = wh & 7;
            float val = -1e30f;
            if (row < NTOK && col < NTOK) {
                int r = row * NTOK + col;
                int ri = __ldg(rel_index + r);
                val = __ldg(mask + w * (NTOK * NTOK) + r)
                    + __ldg(bias_table + ri * NH + h);
            }
            g_bm[idx] = val;
        }
    }
}

// ---------------- kernel 2/4: flat split-bf16 GEMM via mma.sync --------------
#define SA_HI 0
#define SA_LO 69632
#define SB    139264
#define SMB   221184
#define GEMM_SMEM 221248

__global__ __launch_bounds__(256, 1)
void gemm_hmma(const float* __restrict__ x, const float* __restrict__ bias,
               float* __restrict__ out, int which) {
    extern __shared__ __align__(128) char smem[];
    const uint32_t sb = smem_u32(smem);
    const int tid = threadIdx.x, wid = tid >> 5, lane = tid & 31;

    const int nc = which ? PROJ_NC : QKV_NC;
    const __nv_bfloat16* Whi = which ? g_wp_hi : g_wq_hi;
    const __nv_bfloat16* Wlo = which ? g_wp_lo : g_wq_lo;
    const float* A_src = which ? g_attn : x;
    float* dst = which ? out : g_qkv;
    const int dstride = which ? 256 : 768;

    if (tid == 0) {
        MBAR_INIT(sb + SMB, 1);
        MBAR_INIT(sb + SMB + 8, 1);
        #pragma unroll
        for (int i = 0; i < 2 && i < nc; i++) {
            uint32_t mb = sb + SMB + i * 8;
            MBAR_EXPECT_TX(mb, 2 * CH_BYTES);
            uint32_t d = sb + SB + i * (2 * CH_BYTES);
            BULK_G2S(d,            (const void*)(Whi + i * CH_ELEMS), CH_BYTES, mb);
            BULK_G2S(d + CH_BYTES, (const void*)(Wlo + i * CH_ELEMS), CH_BYTES, mb);
        }
    }

    {
        const float4* a4 = (const float4*)(A_src + (size_t)blockIdx.x * 128 * 256);
        #pragma unroll 4
        for (int it = 0; it < 32; it++) {
            int e = it * 256 + tid;
            int row = e >> 6;
            int k4 = (e & 63) * 4;
            float4 v = __ldg(a4 + e);
            __nv_bfloat16 h0 = __float2bfloat16(v.x);
            __nv_bfloat16 h1 = __float2bfloat16(v.y);
            __nv_bfloat16 h2 = __float2bfloat16(v.z);
            __nv_bfloat16 h3 = __float2bfloat16(v.w);
            __nv_bfloat16 l0 = __float2bfloat16(v.x - __bfloat162float(h0));
            __nv_bfloat16 l1 = __float2bfloat16(v.y - __bfloat162float(h1));
            __nv_bfloat16 l2 = __float2bfloat16(v.z - __bfloat162float(h2));
            __nv_bfloat16 l3 = __float2bfloat16(v.w - __bfloat162float(h3));
            uint32_t off = (uint32_t)row * 544 + (uint32_t)k4 * 2;
            uint2 hv, lv;
            hv.x = ((uint32_t)__bfloat16_as_ushort(h1) << 16) | __bfloat16_as_ushort(h0);
            hv.y = ((uint32_t)__bfloat16_as_ushort(h3) << 16) | __bfloat16_as_ushort(h2);
            lv.x = ((uint32_t)__bfloat16_as_ushort(l1) << 16) | __bfloat16_as_ushort(l0);
            lv.y = ((uint32_t)__bfloat16_as_ushort(l3) << 16) | __bfloat16_as_ushort(l2);
            *(uint2*)(smem + SA_HI + off) = hv;
            *(uint2*)(smem + SA_LO + off) = lv;
        }
    }
    __syncthreads();

    const int warp_m = wid & 3, warp_n = wid >> 2;
    const int m0 = warp_m * 32, n0 = warp_n * 16;
    const int lr = lane & 15, lc = lane >> 4;
    const uint32_t a_off = sb + (uint32_t)(m0 + lr) * 544 + (uint32_t)lc * 16;
    const uint32_t b_off = (uint32_t)lr * 80 + (uint32_t)n0 * 2;

    const size_t row_base = (size_t)blockIdx.x * 128;

    for (int c = 0; c < nc; c++) {
        const int buf = c & 1;
        MBAR_WAIT(sb + SMB + buf * 8, (c >> 1) & 1);
        const uint32_t Bb = sb + SB + buf * (2 * CH_BYTES) + b_off;

        float acc[2][2][4];
        #pragma unroll
        for (int mf = 0; mf < 2; mf++)
            #pragma unroll
            for (int nf = 0; nf < 2; nf++)
                #pragma unroll
                for (int i = 0; i < 4; i++) acc[mf][nf][i] = 0.0f;

        #pragma unroll 4
        for (int ks = 0; ks < 16; ks++) {
            uint32_t ah[2][4], al[2][4], bh[2][2], bl[2][2];
            #pragma unroll
            for (int mf = 0; mf < 2; mf++) {
                uint32_t aa = a_off + (uint32_t)mf * (16 * 544) + (uint32_t)ks * 32;
                LDSM_X4(ah[mf], aa + SA_HI);
                LDSM_X4(al[mf], aa + SA_LO);
            }
            #pragma unroll
            for (int nf = 0; nf < 2; nf++) {
                uint32_t ba = Bb + (uint32_t)ks * (16 * 80) + (uint32_t)nf * 16;
                LDSM_X2T(bh[nf], ba);
                LDSM_X2T(bl[nf], ba + CH_BYTES);
            }
            // term-major order: 4 independent accs between reuses of one acc
            #pragma unroll
            for (int mf = 0; mf < 2; mf++)
                #pragma unroll
                for (int nf = 0; nf < 2; nf++)
                    MMA16816(acc[mf][nf], ah[mf], bh[nf]);
            #pragma unroll
            for (int mf = 0; mf < 2; mf++)
                #pragma unroll
                for (int nf = 0; nf < 2; nf++)
                    MMA16816(acc[mf][nf], al[mf], bh[nf]);
            #pragma unroll
            for (int mf = 0; mf < 2; mf++)
                #pragma unroll
                for (int nf = 0; nf < 2; nf++)
                    MMA16816(acc[mf][nf], ah[mf], bl[nf]);
        }

        const float sc = (!which && c < 8) ? ATT_SCALE : 1.0f;
        const int colb = c * 32 + n0 + 2 * (lane & 3);
        const size_t rowb = row_base + m0 + (lane >> 2);
        #pragma unroll
        for (int mf = 0; mf < 2; mf++) {
            #pragma unroll
            for (int nf = 0; nf < 2; nf++) {
                int cc = colb + nf * 8;
                float b0 = __ldg(bias + cc), b1 = __ldg(bias + cc + 1);
                size_t r0 = rowb + mf * 16;
                float2 o0 = make_float2((acc[mf][nf][0] + b0) * sc,
                                        (acc[mf][nf][1] + b1) * sc);
                float2 o1 = make_float2((acc[mf][nf][2] + b0) * sc,
                                        (acc[mf][nf][3] + b1) * sc);
                *(float2*)(dst + r0 * dstride + cc) = o0;
                *(float2*)(dst + (r0 + 8) * dstride + cc) = o1;
            }
        }
        __syncthreads();
        if (tid == 0 && c + 2 < nc) {
            uint32_t mb = sb + SMB + buf * 8;
            MBAR_EXPECT_TX(mb, 2 * CH_BYTES);
            uint32_t d = sb + SB + buf * (2 * CH_BYTES);
            BULK_G2S(d,            (const void*)(Whi + (c + 2) * CH_ELEMS), CH_BYTES, mb);
            BULK_G2S(d + CH_BYTES, (const void*)(Wlo + (c + 2) * CH_ELEMS), CH_BYTES, mb);
        }
    }
}

// ---------------- kernel 3: attention via HMMA ----------------
#define AH_BYTES 27648
#define AKT_OFF  10240
#define AV_OFF   17408
#define ATT_SMEM (8 * AH_BYTES)          // 221184

__global__ __launch_bounds__(256, 1)
void attn_hmma(int nW) {
    extern __shared__ __align__(128) char am[];
    const uint32_t sb = smem_u32(am);
    const int tid = threadIdx.x, wid = tid >> 5, lane = tid & 31;
    const int lr = lane & 15, lc = lane >> 4;
    const int rr = lane >> 2, c2 = 2 * (lane & 3);
    const int b = blockIdx.x;
    const size_t base = (size_t)b * NTOK;
    const float* qkvw = g_qkv + base * 768;

    // ---- cooperative load of all 8 head slots ----
    #pragma unroll 1
    for (int s = 0; s < 8; s++) {
        char* hq = am + s * AH_BYTES;
        const float* qsrc = qkvw + s * HD;
        #pragma unroll
        for (int it = 0; it < 8; it++) {            // q & v: 64x32 (pad rows 0)
            int i = it * 256 + tid;
            int m = i >> 5, d = i & 31;
            float qv = 0.0f, vv = 0.0f;
            if (m < NTOK) {
                qv = __ldg(qsrc + (size_t)m * 768 + d);
                vv = __ldg(qsrc + 512 + (size_t)m * 768 + d);
            }
            __nv_bfloat16 qh = __float2bfloat16(qv);
            __nv_bfloat16 ql = __float2bfloat16(qv - __bfloat162float(qh));
            __nv_bfloat16 vh = __float2bfloat16(vv);
            __nv_bfloat16 vl = __float2bfloat16(vv - __bfloat162float(vh));
            int off = m * 80 + d * 2;
            *(__nv_bfloat16*)(hq + off) = qh;
            *(__nv_bfloat16*)(hq + 5120 + off) = ql;
            *(__nv_bfloat16*)(hq + AV_OFF + off) = vh;
            *(__nv_bfloat16*)(hq + AV_OFF + 5120 + off) = vl;
        }
        #pragma unroll
        for (int it = 0; it < 7; it++) {            // kT: [d][tok], 49 + 7 pad
            int i = it * 256 + tid;
            int m = i >> 5, d = i & 31;
            if (m < 56) {
                float kv = (m < NTOK)
                    ? __ldg(qsrc + 256 + (size_t)m * 768 + d) : 0.0f;
                __nv_bfloat16 kh = __float2bfloat16(kv);
                __nv_bfloat16 kl = __float2bfloat16(kv - __bfloat162float(kh));
                int off = (d * 56 + m) * 2;
                *(__nv_bfloat16*)(hq + AKT_OFF + off) = kh;
                *(__nv_bfloat16*)(hq + AKT_OFF + 3584 + off) = kl;
            }
        }
    }
    __syncthreads();

    const uint32_t hb = sb + wid * AH_BYTES;

    // ---- S = Q * K^T  (M=64, N=56, K=32, 3-term split, term-major) ----
    float acc[4][7][4];
    #pragma unroll
    for (int mf = 0; mf < 4; mf++)
        #pragma unroll
        for (int nf = 0; nf < 7; nf++)
            #pragma unroll
            for (int i = 0; i < 4; i++) acc[mf][nf][i] = 0.0f;

    #pragma unroll
    for (int kk = 0; kk < 2; kk++) {
        uint32_t kfh[7][2], kfl[7][2];
        #pragma unroll
        for (int nf = 0; nf < 7; nf++) {
            uint32_t ba = hb + AKT_OFF + (uint32_t)(kk * 16 + lr) * 112
                        + (uint32_t)nf * 16;
            LDSM_X2T(kfh[nf], ba);
            LDSM_X2T(kfl[nf], ba + 3584);
        }
        #pragma unroll
        for (int mf = 0; mf < 4; mf++) {
            uint32_t ah[4], al[4];
            uint32_t aa = hb + (uint32_t)(mf * 16 + lr) * 80
                        + (uint32_t)(kk * 32) + (uint32_t)lc * 16;
            LDSM_X4(ah, aa);
            LDSM_X4(al, aa + 5120);
            // term-major: 7 independent accs between reuses
            #pragma unroll
            for (int nf = 0; nf < 7; nf++) MMA16816(acc[mf][nf], ah, kfh[nf]);
            #pragma unroll
            for (int nf = 0; nf < 7; nf++) MMA16816(acc[mf][nf], al, kfh[nf]);
            #pragma unroll
            for (int nf = 0; nf < 7; nf++) MMA16816(acc[mf][nf], ah, kfl[nf]);
        }
    }

    const float* bmf = g_bm + ((size_t)(b % nW) * NH + wid) * BMF_PER_WH;
    float* og = g_attn + base * 256 + wid * HD;

    // ---- per mf: bias, softmax in fragments, pack P, P*V, store ----
    #pragma unroll
    for (int mf = 0; mf < 4; mf++) {
        #pragma unroll
        for (int nf = 0; nf < 7; nf++) {
            const float* bp = bmf + ((mf * 7 + nf) * 4) * 32 + lane;
            acc[mf][nf][0] += __ldg(bp);
            acc[mf][nf][1] += __ldg(bp + 32);
            acc[mf][nf][2] += __ldg(bp + 64);
            acc[mf][nf][3] += __ldg(bp + 96);
        }
        float m1 = -1e30f, m2 = -1e30f;
        #pragma unroll
        for (int nf = 0; nf < 7; nf++) {
            m1 = fmaxf(m1, fmaxf(acc[mf][nf][0], acc[mf][nf][1]));
            m2 = fmaxf(m2, fmaxf(acc[mf][nf][2], acc[mf][nf][3]));
        }
        m1 = fmaxf(m1, __shfl_xor_sync(0xffffffffu, m1, 1));
        m1 = fmaxf(m1, __shfl_xor_sync(0xffffffffu, m1, 2));
        m2 = fmaxf(m2, __shfl_xor_sync(0xffffffffu, m2, 1));
        m2 = fmaxf(m2, __shfl_xor_sync(0xffffffffu, m2, 2));
        float s1 = 0.0f, s2 = 0.0f;
        #pragma unroll
        for (int nf = 0; nf < 7; nf++) {
            acc[mf][nf][0] = __expf(acc[mf][nf][0] - m1);
            acc[mf][nf][1] = __expf(acc[mf][nf][1] - m1);
            acc[mf][nf][2] = __expf(acc[mf][nf][2] - m2);
            acc[mf][nf][3] = __expf(acc[mf][nf][3] - m2);
            s1 += acc[mf][nf][0] + acc[mf][nf][1];
            s2 += acc[mf][nf][2] + acc[mf][nf][3];
        }
        s1 += __shfl_xor_sync(0xffffffffu, s1, 1);
        s1 += __shfl_xor_sync(0xffffffffu, s1, 2);
        s2 += __shfl_xor_sync(0xffffffffu, s2, 1);
        s2 += __shfl_xor_sync(0xffffffffu, s2, 2);
        const float inv1 = 1.0f / s1, inv2 = 1.0f / s2;

        // O = P * V (K=64 via 4 k16 blocks; term-major over 4 nf accs)
        float o[4][4];
        #pragma unroll
        for (int nf = 0; nf < 4; nf++)
            #pragma unroll
            for (int i = 0; i < 4; i++) o[nf][i] = 0.0f;

        #pragma unroll
        for (int kk = 0; kk < 4; kk++) {
            uint32_t ph[4], pl[4];
            sp2(acc[mf][2 * kk][0], acc[mf][2 * kk][1], ph[0], pl[0]);
            sp2(acc[mf][2 * kk][2], acc[mf][2 * kk][3], ph[1], pl[1]);
            if (kk < 3) {
                sp2(acc[mf][2 * kk + 1][0], acc[mf][2 * kk + 1][1], ph[2], pl[2]);
                sp2(acc[mf][2 * kk + 1][2], acc[mf][2 * kk + 1][3], ph[3], pl[3]);
            } else {
                ph[2] = 0u; pl[2] = 0u; ph[3] = 0u; pl[3] = 0u;
            }
            uint32_t vh[4][2], vl[4][2];
            #pragma unroll
            for (int nf = 0; nf < 4; nf++) {
                uint32_t ba = hb + AV_OFF + (uint32_t)(kk * 16 + lr) * 80
                            + (uint32_t)nf * 16;
                LDSM_X2T(vh[nf], ba);
                LDSM_X2T(vl[nf], ba + 5120);
            }
            #pragma unroll
            for (int nf = 0; nf < 4; nf++) MMA16816(o[nf], ph, vh[nf]);
            #pragma unroll
            for (int nf = 0; nf < 4; nf++) MMA16816(o[nf], pl, vh[nf]);
            #pragma unroll
            for (int nf = 0; nf < 4; nf++) MMA16816(o[nf], ph, vl[nf]);
        }

        const int r1 = mf * 16 + rr, r2 = r1 + 8;
        #pragma unroll
        for (int nf = 0; nf < 4; nf++) {
            if (r1 < NTOK) {
                float2 v0 = make_float2(o[nf][0] * inv1, o[nf][1] * inv1);
                *(float2*)(og + (size_t)r1 * 256 + nf * 8 + c2) = v0;
            }
            if (r2 < NTOK) {
                float2 v1 = make_float2(o[nf][2] * inv2, o[nf][3] * inv2);
                *(float2*)(og + (size_t)r2 * 256 + nf * 8 + c2) = v1;
            }
        }
    }
}

// ---------------- launch ----------------
extern "C" void kernel_launch(void* const* d_in, const int* in_sizes, int n_in,
                              void* d_out, int out_size) {
    const float* x          = (const float*)d_in[0];
    const float* mask       = (const float*)d_in[1];
    const float* qkv_w      = (const float*)d_in[2];
    const float* qkv_b      = (const float*)d_in[3];
    const float* proj_w     = (const float*)d_in[4];
    const float* proj_b     = (const float*)d_in[5];
    const float* bias_table = (const float*)d_in[6];
    const int*   rel_index  = (const int*)d_in[7];
    float* out = (float*)d_out;

    const int nW = in_sizes[1] / (NTOK * NTOK);     // 64

    cudaFuncSetAttribute(gemm_hmma,
                         cudaFuncAttributeMaxDynamicSharedMemorySize, GEMM_SMEM);
    cudaFuncSetAttribute(attn_hmma,
                         cudaFuncAttributeMaxDynamicSharedMemorySize, ATT_SMEM);

    prep_weights<<<QKV_NC + PROJ_NC + 72, 256>>>(qkv_w, proj_w, mask,
                                                 bias_table, rel_index, nW);
    gemm_hmma<<<NTILES, 256, GEMM_SMEM>>>(x, qkv_b, nullptr, 0);
    attn_hmma<<<2048, 256, ATT_SMEM>>>(nW);
    gemm_hmma<<<NTILES, 256, GEMM_SMEM>>>(nullptr, proj_b, out, 1);
}

// round 15
// speedup vs baseline: 1.0387x; 1.0387x over previous
#include <cuda_runtime.h>
#include <cuda_bf16.h>
#include <cstdint>

#define NTOK 49
#define DIMC 256
#define NH   8
#define HD   32
#define ATT_SCALE 0.17677669529663687f   // 32^-0.5

#define TOKENS   100352                  // 2048 * 49
#define NTILES   784                     // TOKENS / 128
#define QKV_NC   24                      // 768 / 32
#define PROJ_NC  8                       // 256 / 32
#define CH_ELEMS 10240                   // 256 rows * 40 (32 data + 8 pad) bf16
#define CH_BYTES 20480
#define NWMAX    64
#define BMF_PER_WH 3584                  // 4mf * 7nf * 4j * 32lane

// ---------------- global scratch (static, no allocs) ----------------
__device__ __align__(128) float g_qkv[(size_t)TOKENS * 768];
__device__ __align__(128) float g_attn[(size_t)TOKENS * 256];
__device__ __align__(128) float g_bm[(size_t)NWMAX * NH * BMF_PER_WH];
__device__ __align__(128) __nv_bfloat16 g_wq_hi[QKV_NC * CH_ELEMS];
__device__ __align__(128) __nv_bfloat16 g_wq_lo[QKV_NC * CH_ELEMS];
__device__ __align__(128) __nv_bfloat16 g_wp_hi[PROJ_NC * CH_ELEMS];
__device__ __align__(128) __nv_bfloat16 g_wp_lo[PROJ_NC * CH_ELEMS];

// ---------------- ptx helpers ----------------
__device__ __forceinline__ uint32_t smem_u32(const void* p) {
    uint32_t a;
    asm("{ .reg .u64 t; cvta.to.shared.u64 t, %1; cvt.u32.u64 %0, t; }"
        : "=r"(a) : "l"(p));
    return a;
}

#define MBAR_INIT(a, c) \
    asm volatile("mbarrier.init.shared.b64 [%0], %1;" :: "r"(a), "r"(c) : "memory")
#define MBAR_EXPECT_TX(a, b) \
    asm volatile("mbarrier.arrive.expect_tx.shared.b64 _, [%0], %1;" :: "r"(a), "r"(b) : "memory")
#define MBAR_WAIT(a, ph) do { \
    uint32_t _m = (a); uint32_t _p = (ph); uint32_t _d; \
    asm volatile("{\n\t.reg .pred p;\n\t" \
        "mbarrier.try_wait.parity.acquire.cta.shared::cta.b64 p, [%1], %2;\n\t" \
        "selp.b32 %0, 1, 0, p;\n\t}" : "=r"(_d) : "r"(_m), "r"(_p) : "memory"); \
    if (!_d) { \
        asm volatile("{\n\t.reg .pred P1;\n\tWL_%=:\n\t" \
            "mbarrier.try_wait.parity.acquire.cta.shared::cta.b64 P1, [%0], %1, 0x989680;\n\t" \
            "@P1 bra.uni WD_%=;\n\tbra.uni WL_%=;\n\tWD_%=:\n\t}" \
            :: "r"(_m), "r"(_p) : "memory"); \
    } } while (0)

#define BULK_G2S(dst, src, bytes, mbar) \
    asm volatile("cp.async.bulk.shared::cluster.global.mbarrier::complete_tx::bytes " \
                 "[%0], [%1], %2, [%3];" \
                 :: "r"(dst), "l"(src), "r"(bytes), "r"(mbar) : "memory")

#define LDSM_X4(r, addr) \
    asm volatile("ldmatrix.sync.aligned.m8n8.x4.shared.b16 {%0,%1,%2,%3}, [%4];" \
        : "=r"((r)[0]), "=r"((r)[1]), "=r"((r)[2]), "=r"((r)[3]) : "r"(addr))

#define LDSM_X2T(r, addr) \
    asm volatile("ldmatrix.sync.aligned.m8n8.x2.trans.shared.b16 {%0,%1}, [%2];" \
        : "=r"((r)[0]), "=r"((r)[1]) : "r"(addr))

#define MMA16816(c, a, b) \
    asm volatile("mma.sync.aligned.m16n8k16.row.col.f32.bf16.bf16.f32 " \
        "{%0,%1,%2,%3}, {%4,%5,%6,%7}, {%8,%9}, {%0,%1,%2,%3};" \
        : "+f"((c)[0]), "+f"((c)[1]), "+f"((c)[2]), "+f"((c)[3]) \
        : "r"((a)[0]), "r"((a)[1]), "r"((a)[2]), "r"((a)[3]), \
          "r"((b)[0]), "r"((b)[1]))

// split x,y to bf16 hi/lo packed pairs (x in low half)
__device__ __forceinline__ void sp2(float x, float y, uint32_t& h, uint32_t& l) {
    __nv_bfloat16 hx = __float2bfloat16(x), hy = __float2bfloat16(y);
    __nv_bfloat16 lx = __float2bfloat16(x - __bfloat162float(hx));
    __nv_bfloat16 ly = __float2bfloat16(y - __bfloat162float(hy));
    h = ((uint32_t)__bfloat16_as_ushort(hy) << 16) | __bfloat16_as_ushort(hx);
    l = ((uint32_t)__bfloat16_as_ushort(ly) << 16) | __bfloat16_as_ushort(lx);
}

// ---------------- kernel 1: weight prep + fragment-ordered bias/mask ---------
__global__ void prep_weights(const float* __restrict__ qkv_w,
                             const float* __restrict__ proj_w,
                             const float* __restrict__ mask,
                             const float* __restrict__ bias_table,
                             const int*   __restrict__ rel_index,
                             int nW) {
    int c = blockIdx.x;
    if (c < QKV_NC + PROJ_NC) {
        bool isq = c < QKV_NC;
        int chunk = isq ? c : c - QKV_NC;
        const float* W = isq ? qkv_w : proj_w;
        int ncols = isq ? 768 : 256;
        __nv_bfloat16* hi = (isq ? g_wq_hi : g_wp_hi) + chunk * CH_ELEMS;
        __nv_bfloat16* lo = (isq ? g_wq_lo : g_wp_lo) + chunk * CH_ELEMS;
        for (int idx = threadIdx.x; idx < CH_ELEMS; idx += blockDim.x) {
            int k = idx / 40;
            int n = idx - k * 40;
            float w = (n < 32) ? __ldg(W + k * ncols + chunk * 32 + n) : 0.0f;
            __nv_bfloat16 h = __float2bfloat16(w);
            __nv_bfloat16 l = __float2bfloat16(w - __bfloat162float(h));
            hi[idx] = h;
            lo[idx] = l;
        }
    } else {
        // fragment-ordered: g_bm[wh][((mf*7+nf)*4+j)*32+lane]
        int total = nW * NH * BMF_PER_WH;
        int nb = gridDim.x - (QKV_NC + PROJ_NC);
        for (int idx = (c - QKV_NC - PROJ_NC) * blockDim.x + threadIdx.x;
             idx < total; idx += nb * blockDim.x) {
            int wh  = idx / BMF_PER_WH;
            int rem = idx - wh * BMF_PER_WH;
            int lane = rem & 31;
            int t = rem >> 5;
            int j = t & 3;
            int mfnf = t >> 2;
            int nf = mfnf % 7, mf = mfnf / 7;
            int row = mf * 16 + (lane >> 2) + ((j >> 1) << 3);
            int col = nf * 8 + 2 * (lane & 3) + (j & 1);
            int w = wh >> 3, h = wh & 7;
            float val = -1e30f;
            if (row < NTOK && col < NTOK) {
                int r = row * NTOK + col;
                int ri = __ldg(rel_index + r);
                val = __ldg(mask + w * (NTOK * NTOK) + r)
                    + __ldg(bias_table + ri * NH + h);
            }
            g_bm[idx] = val;
        }
    }
}

// ---------------- kernel 2/4: flat split-bf16 GEMM via mma.sync --------------
#define SA_HI 0
#define SA_LO 69632
#define SB    139264
#define SMB   221184
#define GEMM_SMEM 221248

__global__ __launch_bounds__(256, 1)
void gemm_hmma(const float* __restrict__ x, const float* __restrict__ bias,
               float* __restrict__ out, int which) {
    extern __shared__ __align__(128) char smem[];
    const uint32_t sb = smem_u32(smem);
    const int tid = threadIdx.x, wid = tid >> 5, lane = tid & 31;

    const int nc = which ? PROJ_NC : QKV_NC;
    const __nv_bfloat16* Whi = which ? g_wp_hi : g_wq_hi;
    const __nv_bfloat16* Wlo = which ? g_wp_lo : g_wq_lo;
    const float* A_src = which ? g_attn : x;
    float* dst = which ? out : g_qkv;
    const int dstride = which ? 256 : 768;

    if (tid == 0) {
        MBAR_INIT(sb + SMB, 1);
        MBAR_INIT(sb + SMB + 8, 1);
        #pragma unroll
        for (int i = 0; i < 2 && i < nc; i++) {
            uint32_t mb = sb + SMB + i * 8;
            MBAR_EXPECT_TX(mb, 2 * CH_BYTES);
            uint32_t d = sb + SB + i * (2 * CH_BYTES);
            BULK_G2S(d,            (const void*)(Whi + i * CH_ELEMS), CH_BYTES, mb);
            BULK_G2S(d + CH_BYTES, (const void*)(Wlo + i * CH_ELEMS), CH_BYTES, mb);
        }
    }

    {
        const float4* a4 = (const float4*)(A_src + (size_t)blockIdx.x * 128 * 256);
        #pragma unroll 4
        for (int it = 0; it < 32; it++) {
            int e = it * 256 + tid;
            int row = e >> 6;
            int k4 = (e & 63) * 4;
            float4 v = __ldg(a4 + e);
            __nv_bfloat16 h0 = __float2bfloat16(v.x);
            __nv_bfloat16 h1 = __float2bfloat16(v.y);
            __nv_bfloat16 h2 = __float2bfloat16(v.z);
            __nv_bfloat16 h3 = __float2bfloat16(v.w);
            __nv_bfloat16 l0 = __float2bfloat16(v.x - __bfloat162float(h0));
            __nv_bfloat16 l1 = __float2bfloat16(v.y - __bfloat162float(h1));
            __nv_bfloat16 l2 = __float2bfloat16(v.z - __bfloat162float(h2));
            __nv_bfloat16 l3 = __float2bfloat16(v.w - __bfloat162float(h3));
            uint32_t off = (uint32_t)row * 544 + (uint32_t)k4 * 2;
            uint2 hv, lv;
            hv.x = ((uint32_t)__bfloat16_as_ushort(h1) << 16) | __bfloat16_as_ushort(h0);
            hv.y = ((uint32_t)__bfloat16_as_ushort(h3) << 16) | __bfloat16_as_ushort(h2);
            lv.x = ((uint32_t)__bfloat16_as_ushort(l1) << 16) | __bfloat16_as_ushort(l0);
            lv.y = ((uint32_t)__bfloat16_as_ushort(l3) << 16) | __bfloat16_as_ushort(l2);
            *(uint2*)(smem + SA_HI + off) = hv;
            *(uint2*)(smem + SA_LO + off) = lv;
        }
    }
    __syncthreads();

    const int warp_m = wid & 3, warp_n = wid >> 2;
    const int m0 = warp_m * 32, n0 = warp_n * 16;
    const int lr = lane & 15, lc = lane >> 4;
    const uint32_t a_off = sb + (uint32_t)(m0 + lr) * 544 + (uint32_t)lc * 16;
    const uint32_t b_off = (uint32_t)lr * 80 + (uint32_t)n0 * 2;

    const size_t row_base = (size_t)blockIdx.x * 128;

    for (int c = 0; c < nc; c++) {
        const int buf = c & 1;
        MBAR_WAIT(sb + SMB + buf * 8, (c >> 1) & 1);
        const uint32_t Bb = sb + SB + buf * (2 * CH_BYTES) + b_off;

        float acc[2][2][4];
        #pragma unroll
        for (int mf = 0; mf < 2; mf++)
            #pragma unroll
            for (int nf = 0; nf < 2; nf++)
                #pragma unroll
                for (int i = 0; i < 4; i++) acc[mf][nf][i] = 0.0f;

        // software-pipelined mainloop: fragment reg double-buffer
        uint32_t ah[2][2][4], al[2][2][4], bh[2][2][2], bl[2][2][2];

        #define GEMM_LOAD_KS(B, KS) do { \
            _Pragma("unroll") \
            for (int mf = 0; mf < 2; mf++) { \
                uint32_t aa = a_off + (uint32_t)mf * (16 * 544) + (uint32_t)(KS) * 32; \
                LDSM_X4(ah[B][mf], aa + SA_HI); \
                LDSM_X4(al[B][mf], aa + SA_LO); \
            } \
            _Pragma("unroll") \
            for (int nf = 0; nf < 2; nf++) { \
                uint32_t ba = Bb + (uint32_t)(KS) * (16 * 80) + (uint32_t)nf * 16; \
                LDSM_X2T(bh[B][nf], ba); \
                LDSM_X2T(bl[B][nf], ba + CH_BYTES); \
            } \
        } while (0)

        GEMM_LOAD_KS(0, 0);
        #pragma unroll
        for (int ks = 0; ks < 16; ks++) {
            const int cur = ks & 1;
            if (ks < 15) GEMM_LOAD_KS(cur ^ 1, ks + 1);
            #pragma unroll
            for (int mf = 0; mf < 2; mf++)
                #pragma unroll
                for (int nf = 0; nf < 2; nf++)
                    MMA16816(acc[mf][nf], ah[cur][mf], bh[cur][nf]);
            #pragma unroll
            for (int mf = 0; mf < 2; mf++)
                #pragma unroll
                for (int nf = 0; nf < 2; nf++)
                    MMA16816(acc[mf][nf], al[cur][mf], bh[cur][nf]);
            #pragma unroll
            for (int mf = 0; mf < 2; mf++)
                #pragma unroll
                for (int nf = 0; nf < 2; nf++)
                    MMA16816(acc[mf][nf], ah[cur][mf], bl[cur][nf]);
        }
        #undef GEMM_LOAD_KS

        const float sc = (!which && c < 8) ? ATT_SCALE : 1.0f;
        const int colb = c * 32 + n0 + 2 * (lane & 3);
        const size_t rowb = row_base + m0 + (lane >> 2);
        #pragma unroll
        for (int mf = 0; mf < 2; mf++) {
            #pragma unroll
            for (int nf = 0; nf < 2; nf++) {
                int cc = colb + nf * 8;
                float b0 = __ldg(bias + cc), b1 = __ldg(bias + cc + 1);
                size_t r0 = rowb + mf * 16;
                float2 o0 = make_float2((acc[mf][nf][0] + b0) * sc,
                                        (acc[mf][nf][1] + b1) * sc);
                float2 o1 = make_float2((acc[mf][nf][2] + b0) * sc,
                                        (acc[mf][nf][3] + b1) * sc);
                *(float2*)(dst + r0 * dstride + cc) = o0;
                *(float2*)(dst + (r0 + 8) * dstride + cc) = o1;
            }
        }
        __syncthreads();
        if (tid == 0 && c + 2 < nc) {
            uint32_t mb = sb + SMB + buf * 8;
            MBAR_EXPECT_TX(mb, 2 * CH_BYTES);
            uint32_t d = sb + SB + buf * (2 * CH_BYTES);
            BULK_G2S(d,            (const void*)(Whi + (c + 2) * CH_ELEMS), CH_BYTES, mb);
            BULK_G2S(d + CH_BYTES, (const void*)(Wlo + (c + 2) * CH_ELEMS), CH_BYTES, mb);
        }
    }
}

// ---------------- kernel 3: attention via HMMA ----------------
#define AH_BYTES 27648
#define AKT_OFF  10240
#define AV_OFF   17408
#define ATT_SMEM (8 * AH_BYTES)          // 221184

__global__ __launch_bounds__(256, 1)
void attn_hmma(int nW) {
    extern __shared__ __align__(128) char am[];
    const uint32_t sb = smem_u32(am);
    const int tid = threadIdx.x, wid = tid >> 5, lane = tid & 31;
    const int lr = lane & 15, lc = lane >> 4;
    const int rr = lane >> 2, c2 = 2 * (lane & 3);
    const int b = blockIdx.x;
    const size_t base = (size_t)b * NTOK;
    const float* qkvw = g_qkv + base * 768;

    // ---- cooperative load of all 8 head slots ----
    #pragma unroll 1
    for (int s = 0; s < 8; s++) {
        char* hq = am + s * AH_BYTES;
        const float* qsrc = qkvw + s * HD;
        #pragma unroll
        for (int it = 0; it < 8; it++) {            // q & v: 64x32 (pad rows 0)
            int i = it * 256 + tid;
            int m = i >> 5, d = i & 31;
            float qv = 0.0f, vv = 0.0f;
            if (m < NTOK) {
                qv = __ldg(qsrc + (size_t)m * 768 + d);
                vv = __ldg(qsrc + 512 + (size_t)m * 768 + d);
            }
            __nv_bfloat16 qh = __float2bfloat16(qv);
            __nv_bfloat16 ql = __float2bfloat16(qv - __bfloat162float(qh));
            __nv_bfloat16 vh = __float2bfloat16(vv);
            __nv_bfloat16 vl = __float2bfloat16(vv - __bfloat162float(vh));
            int off = m * 80 + d * 2;
            *(__nv_bfloat16*)(hq + off) = qh;
            *(__nv_bfloat16*)(hq + 5120 + off) = ql;
            *(__nv_bfloat16*)(hq + AV_OFF + off) = vh;
            *(__nv_bfloat16*)(hq + AV_OFF + 5120 + off) = vl;
        }
        #pragma unroll
        for (int it = 0; it < 7; it++) {            // kT: [d][tok], 49 + 7 pad
            int i = it * 256 + tid;
            int m = i >> 5, d = i & 31;
            if (m < 56) {
                float kv = (m < NTOK)
                    ? __ldg(qsrc + 256 + (size_t)m * 768 + d) : 0.0f;
                __nv_bfloat16 kh = __float2bfloat16(kv);
                __nv_bfloat16 kl = __float2bfloat16(kv - __bfloat162float(kh));
                int off = (d * 56 + m) * 2;
                *(__nv_bfloat16*)(hq + AKT_OFF + off) = kh;
                *(__nv_bfloat16*)(hq + AKT_OFF + 3584 + off) = kl;
            }
        }
    }
    __syncthreads();

    const uint32_t hb = sb + wid * AH_BYTES;

    // ---- S = Q * K^T  (M=64, N=56, K=32, 3-term split, pipelined A) ----
    float acc[4][7][4];
    #pragma unroll
    for (int mf = 0; mf < 4; mf++)
        #pragma unroll
        for (int nf = 0; nf < 7; nf++)
            #pragma unroll
            for (int i = 0; i < 4; i++) acc[mf][nf][i] = 0.0f;

    #pragma unroll
    for (int kk = 0; kk < 2; kk++) {
        uint32_t kfh[7][2], kfl[7][2];
        #pragma unroll
        for (int nf = 0; nf < 7; nf++) {
            uint32_t ba = hb + AKT_OFF + (uint32_t)(kk * 16 + lr) * 112
                        + (uint32_t)nf * 16;
            LDSM_X2T(kfh[nf], ba);
            LDSM_X2T(kfl[nf], ba + 3584);
        }
        uint32_t ah[2][4], al[2][4];
        {
            uint32_t aa0 = hb + (uint32_t)lr * 80 + (uint32_t)(kk * 32)
                         + (uint32_t)lc * 16;
            LDSM_X4(ah[0], aa0);
            LDSM_X4(al[0], aa0 + 5120);
        }
        #pragma unroll
        for (int mf = 0; mf < 4; mf++) {
            const int cur = mf & 1;
            if (mf < 3) {
                uint32_t aa = hb + (uint32_t)((mf + 1) * 16 + lr) * 80
                            + (uint32_t)(kk * 32) + (uint32_t)lc * 16;
                LDSM_X4(ah[cur ^ 1], aa);
                LDSM_X4(al[cur ^ 1], aa + 5120);
            }
            #pragma unroll
            for (int nf = 0; nf < 7; nf++) MMA16816(acc[mf][nf], ah[cur], kfh[nf]);
            #pragma unroll
            for (int nf = 0; nf < 7; nf++) MMA16816(acc[mf][nf], al[cur], kfh[nf]);
            #pragma unroll
            for (int nf = 0; nf < 7; nf++) MMA16816(acc[mf][nf], ah[cur], kfl[nf]);
        }
    }

    const float* bmf = g_bm + ((size_t)(b % nW) * NH + wid) * BMF_PER_WH;
    float* og = g_attn + base * 256 + wid * HD;

    // ---- per mf: bias, softmax in fragments, pack P, P*V, store ----
    #pragma unroll
    for (int mf = 0; mf < 4; mf++) {
        #pragma unroll
        for (int nf = 0; nf < 7; nf++) {
            const float* bp = bmf + ((mf * 7 + nf) * 4) * 32 + lane;
            acc[mf][nf][0] += __ldg(bp);
            acc[mf][nf][1] += __ldg(bp + 32);
            acc[mf][nf][2] += __ldg(bp + 64);
            acc[mf][nf][3] += __ldg(bp + 96);
        }
        float m1 = -1e30f, m2 = -1e30f;
        #pragma unroll
        for (int nf = 0; nf < 7; nf++) {
            m1 = fmaxf(m1, fmaxf(acc[mf][nf][0], acc[mf][nf][1]));
            m2 = fmaxf(m2, fmaxf(acc[mf][nf][2], acc[mf][nf][3]));
        }
        m1 = fmaxf(m1, __shfl_xor_sync(0xffffffffu, m1, 1));
        m1 = fmaxf(m1, __shfl_xor_sync(0xffffffffu, m1, 2));
        m2 = fmaxf(m2, __shfl_xor_sync(0xffffffffu, m2, 1));
        m2 = fmaxf(m2, __shfl_xor_sync(0xffffffffu, m2, 2));
        float s1 = 0.0f, s2 = 0.0f;
        #pragma unroll
        for (int nf = 0; nf < 7; nf++) {
            acc[mf][nf][0] = __expf(acc[mf][nf][0] - m1);
            acc[mf][nf][1] = __expf(acc[mf][nf][1] - m1);
            acc[mf][nf][2] = __expf(acc[mf][nf][2] - m2);
            acc[mf][nf][3] = __expf(acc[mf][nf][3] - m2);
            s1 += acc[mf][nf][0] + acc[mf][nf][1];
            s2 += acc[mf][nf][2] + acc[mf][nf][3];
        }
        s1 += __shfl_xor_sync(0xffffffffu, s1, 1);
        s1 += __shfl_xor_sync(0xffffffffu, s1, 2);
        s2 += __shfl_xor_sync(0xffffffffu, s2, 1);
        s2 += __shfl_xor_sync(0xffffffffu, s2, 2);
        const float inv1 = 1.0f / s1, inv2 = 1.0f / s2;

        // O = P * V (K=64 via 4 k16 blocks; term-major over 4 nf accs)
        float o[4][4];
        #pragma unroll
        for (int nf = 0; nf < 4; nf++)
            #pragma unroll
            for (int i = 0; i < 4; i++) o[nf][i] = 0.0f;

        #pragma unroll
        for (int kk = 0; kk < 4; kk++) {
            uint32_t ph[4], pl[4];
            sp2(acc[mf][2 * kk][0], acc[mf][2 * kk][1], ph[0], pl[0]);
            sp2(acc[mf][2 * kk][2], acc[mf][2 * kk][3], ph[1], pl[1]);
            if (kk < 3) {
                sp2(acc[mf][2 * kk + 1][0], acc[mf][2 * kk + 1][1], ph[2], pl[2]);
                sp2(acc[mf][2 * kk + 1][2], acc[mf][2 * kk + 1][3], ph[3], pl[3]);
            } else {
                ph[2] = 0u; pl[2] = 0u; ph[3] = 0u; pl[3] = 0u;
            }
            uint32_t vh[4][2], vl[4][2];
            #pragma unroll
            for (int nf = 0; nf < 4; nf++) {
                uint32_t ba = hb + AV_OFF + (uint32_t)(kk * 16 + lr) * 80
                            + (uint32_t)nf * 16;
                LDSM_X2T(vh[nf], ba);
                LDSM_X2T(vl[nf], ba + 5120);
            }
            #pragma unroll
            for (int nf = 0; nf < 4; nf++) MMA16816(o[nf], ph, vh[nf]);
            #pragma unroll
            for (int nf = 0; nf < 4; nf++) MMA16816(o[nf], pl, vh[nf]);
            #pragma unroll
            for (int nf = 0; nf < 4; nf++) MMA16816(o[nf], ph, vl[nf]);
        }

        const int r1 = mf * 16 + rr, r2 = r1 + 8;
        #pragma unroll
        for (int nf = 0; nf < 4; nf++) {
            if (r1 < NTOK) {
                float2 v0 = make_float2(o[nf][0] * inv1, o[nf][1] * inv1);
                *(float2*)(og + (size_t)r1 * 256 + nf * 8 + c2) = v0;
            }
            if (r2 < NTOK) {
                float2 v1 = make_float2(o[nf][2] * inv2, o[nf][3] * inv2);
                *(float2*)(og + (size_t)r2 * 256 + nf * 8 + c2) = v1;
            }
        }
    }
}

// ---------------- launch ----------------
extern "C" void kernel_launch(void* const* d_in, const int* in_sizes, int n_in,
                              void* d_out, int out_size) {
    const float* x          = (const float*)d_in[0];
    const float* mask       = (const float*)d_in[1];
    const float* qkv_w      = (const float*)d_in[2];
    const float* qkv_b      = (const float*)d_in[3];
    const float* proj_w     = (const float*)d_in[4];
    const float* proj_b     = (const float*)d_in[5];
    const float* bias_table = (const float*)d_in[6];
    const int*   rel_index  = (const int*)d_in[7];
    float* out = (float*)d_out;

    const int nW = in_sizes[1] / (NTOK * NTOK);     // 64

    cudaFuncSetAttribute(gemm_hmma,
                         cudaFuncAttributeMaxDynamicSharedMemorySize, GEMM_SMEM);
    cudaFuncSetAttribute(attn_hmma,
                         cudaFuncAttributeMaxDynamicSharedMemorySize, ATT_SMEM);

    prep_weights<<<QKV_NC + PROJ_NC + 72, 256>>>(qkv_w, proj_w, mask,
                                                 bias_table, rel_index, nW);
    gemm_hmma<<<NTILES, 256, GEMM_SMEM>>>(x, qkv_b, nullptr, 0);
    attn_hmma<<<2048, 256, ATT_SMEM>>>(nW);
    gemm_hmma<<<NTILES, 256, GEMM_SMEM>>>(nullptr, proj_b, out, 1);
}

// round 16
// speedup vs baseline: 1.2668x; 1.2195x over previous
#include <cuda_runtime.h>
#include <cuda_bf16.h>
#include <cstdint>

#define NTOK 49
#define DIMC 256
#define NH   8
#define HD   32
#define ATT_SCALE 0.17677669529663687f   // 32^-0.5

#define TOKENS   100352                  // 2048 * 49
#define NTILES   784                     // TOKENS / 128
#define QKV_NC   24                      // 768 / 32
#define PROJ_NC  8                       // 256 / 32
#define CH_ELEMS 10240                   // 256 rows * 40 (32 data + 8 pad) bf16
#define CH_BYTES 20480
#define NWMAX    64
#define BMF_PER_WH 3584                  // 4mf * 7nf * 4j * 32lane

// ---------------- global scratch (static, no allocs) ----------------
__device__ __align__(128) float g_qkv[(size_t)TOKENS * 768];
__device__ __align__(128) float g_attn[(size_t)TOKENS * 256];
__device__ __align__(128) float g_bm[(size_t)NWMAX * NH * BMF_PER_WH];
__device__ __align__(128) __nv_bfloat16 g_wq_hi[QKV_NC * CH_ELEMS];
__device__ __align__(128) __nv_bfloat16 g_wq_lo[QKV_NC * CH_ELEMS];
__device__ __align__(128) __nv_bfloat16 g_wp_hi[PROJ_NC * CH_ELEMS];
__device__ __align__(128) __nv_bfloat16 g_wp_lo[PROJ_NC * CH_ELEMS];

// ---------------- ptx helpers ----------------
__device__ __forceinline__ uint32_t smem_u32(const void* p) {
    uint32_t a;
    asm("{ .reg .u64 t; cvta.to.shared.u64 t, %1; cvt.u32.u64 %0, t; }"
        : "=r"(a) : "l"(p));
    return a;
}

#define MBAR_INIT(a, c) \
    asm volatile("mbarrier.init.shared.b64 [%0], %1;" :: "r"(a), "r"(c) : "memory")
#define MBAR_EXPECT_TX(a, b) \
    asm volatile("mbarrier.arrive.expect_tx.shared.b64 _, [%0], %1;" :: "r"(a), "r"(b) : "memory")
#define MBAR_WAIT(a, ph) do { \
    uint32_t _m = (a); uint32_t _p = (ph); uint32_t _d; \
    asm volatile("{\n\t.reg .pred p;\n\t" \
        "mbarrier.try_wait.parity.acquire.cta.shared::cta.b64 p, [%1], %2;\n\t" \
        "selp.b32 %0, 1, 0, p;\n\t}" : "=r"(_d) : "r"(_m), "r"(_p) : "memory"); \
    if (!_d) { \
        asm volatile("{\n\t.reg .pred P1;\n\tWL_%=:\n\t" \
            "mbarrier.try_wait.parity.acquire.cta.shared::cta.b64 P1, [%0], %1, 0x989680;\n\t" \
            "@P1 bra.uni WD_%=;\n\tbra.uni WL_%=;\n\tWD_%=:\n\t}" \
            :: "r"(_m), "r"(_p) : "memory"); \
    } } while (0)

#define BULK_G2S(dst, src, bytes, mbar) \
    asm volatile("cp.async.bulk.shared::cluster.global.mbarrier::complete_tx::bytes " \
                 "[%0], [%1], %2, [%3];" \
                 :: "r"(dst), "l"(src), "r"(bytes), "r"(mbar) : "memory")

#define LDSM_X4(r, addr) \
    asm volatile("ldmatrix.sync.aligned.m8n8.x4.shared.b16 {%0,%1,%2,%3}, [%4];" \
        : "=r"((r)[0]), "=r"((r)[1]), "=r"((r)[2]), "=r"((r)[3]) : "r"(addr))

#define LDSM_X2T(r, addr) \
    asm volatile("ldmatrix.sync.aligned.m8n8.x2.trans.shared.b16 {%0,%1}, [%2];" \
        : "=r"((r)[0]), "=r"((r)[1]) : "r"(addr))

#define MMA16816(c, a, b) \
    asm volatile("mma.sync.aligned.m16n8k16.row.col.f32.bf16.bf16.f32 " \
        "{%0,%1,%2,%3}, {%4,%5,%6,%7}, {%8,%9}, {%0,%1,%2,%3};" \
        : "+f"((c)[0]), "+f"((c)[1]), "+f"((c)[2]), "+f"((c)[3]) \
        : "r"((a)[0]), "r"((a)[1]), "r"((a)[2]), "r"((a)[3]), \
          "r"((b)[0]), "r"((b)[1]))

// split x,y to bf16 hi/lo packed pairs (x in low half)
__device__ __forceinline__ void sp2(float x, float y, uint32_t& h, uint32_t& l) {
    __nv_bfloat16 hx = __float2bfloat16(x), hy = __float2bfloat16(y);
    __nv_bfloat16 lx = __float2bfloat16(x - __bfloat162float(hx));
    __nv_bfloat16 ly = __float2bfloat16(y - __bfloat162float(hy));
    h = ((uint32_t)__bfloat16_as_ushort(hy) << 16) | __bfloat16_as_ushort(hx);
    l = ((uint32_t)__bfloat16_as_ushort(ly) << 16) | __bfloat16_as_ushort(lx);
}

// ---------------- kernel 1: weight prep + fragment-ordered bias/mask ---------
__global__ void prep_weights(const float* __restrict__ qkv_w,
                             const float* __restrict__ proj_w,
                             const float* __restrict__ mask,
                             const float* __restrict__ bias_table,
                             const int*   __restrict__ rel_index,
                             int nW) {
    int c = blockIdx.x;
    if (c < QKV_NC + PROJ_NC) {
        bool isq = c < QKV_NC;
        int chunk = isq ? c : c - QKV_NC;
        const float* W = isq ? qkv_w : proj_w;
        int ncols = isq ? 768 : 256;
        __nv_bfloat16* hi = (isq ? g_wq_hi : g_wp_hi) + chunk * CH_ELEMS;
        __nv_bfloat16* lo = (isq ? g_wq_lo : g_wp_lo) + chunk * CH_ELEMS;
        for (int idx = threadIdx.x; idx < CH_ELEMS; idx += blockDim.x) {
            int k = idx / 40;
            int n = idx - k * 40;
            float w = (n < 32) ? __ldg(W + k * ncols + chunk * 32 + n) : 0.0f;
            __nv_bfloat16 h = __float2bfloat16(w);
            __nv_bfloat16 l = __float2bfloat16(w - __bfloat162float(h));
            hi[idx] = h;
            lo[idx] = l;
        }
    } else {
        // fragment-ordered: g_bm[wh][((mf*7+nf)*4+j)*32+lane]
        int total = nW * NH * BMF_PER_WH;
        int nb = gridDim.x - (QKV_NC + PROJ_NC);
        for (int idx = (c - QKV_NC - PROJ_NC) * blockDim.x + threadIdx.x;
             idx < total; idx += nb * blockDim.x) {
            int wh  = idx / BMF_PER_WH;
            int rem = idx - wh * BMF_PER_WH;
            int lane = rem & 31;
            int t = rem >> 5;
            int j = t & 3;
            int mfnf = t >> 2;
            int nf = mfnf % 7, mf = mfnf / 7;
            int row = mf * 16 + (lane >> 2) + ((j >> 1) << 3);
            int col = nf * 8 + 2 * (lane & 3) + (j & 1);
            int w = wh >> 3, h = wh & 7;
            float val = -1e30f;
            if (row < NTOK && col < NTOK) {
                int r = row * NTOK + col;
                int ri = __ldg(rel_index + r);
                val = __ldg(mask + w * (NTOK * NTOK) + r)
                    + __ldg(bias_table + ri * NH + h);
            }
            g_bm[idx] = val;
        }
    }
}

// ---------------- kernel 2/4: flat split-bf16 GEMM via mma.sync --------------
// Warp tiling 8m x 1n (warp tile m16 x n32). A fragments (m16 x K256, hi/lo)
// are loaded ONCE into 128 registers and reused across all N-chunks.
#define SA_HI 0
#define SA_LO 69632
#define SB    139264
#define SMB   221184
#define GEMM_SMEM 221248

__global__ __launch_bounds__(256, 1)
void gemm_hmma(const float* __restrict__ x, const float* __restrict__ bias,
               float* __restrict__ out, int which) {
    extern __shared__ __align__(128) char smem[];
    const uint32_t sb = smem_u32(smem);
    const int tid = threadIdx.x, wid = tid >> 5, lane = tid & 31;

    const int nc = which ? PROJ_NC : QKV_NC;
    const __nv_bfloat16* Whi = which ? g_wp_hi : g_wq_hi;
    const __nv_bfloat16* Wlo = which ? g_wp_lo : g_wq_lo;
    const float* A_src = which ? g_attn : x;
    float* dst = which ? out : g_qkv;
    const int dstride = which ? 256 : 768;

    if (tid == 0) {
        MBAR_INIT(sb + SMB, 1);
        MBAR_INIT(sb + SMB + 8, 1);
        #pragma unroll
        for (int i = 0; i < 2 && i < nc; i++) {
            uint32_t mb = sb + SMB + i * 8;
            MBAR_EXPECT_TX(mb, 2 * CH_BYTES);
            uint32_t d = sb + SB + i * (2 * CH_BYTES);
            BULK_G2S(d,            (const void*)(Whi + i * CH_ELEMS), CH_BYTES, mb);
            BULK_G2S(d + CH_BYTES, (const void*)(Wlo + i * CH_ELEMS), CH_BYTES, mb);
        }
    }

    // A tile: 128x256 fp32 -> bf16 hi/lo into 544B-stride smem rows
    {
        const float4* a4 = (const float4*)(A_src + (size_t)blockIdx.x * 128 * 256);
        #pragma unroll 4
        for (int it = 0; it < 32; it++) {
            int e = it * 256 + tid;
            int row = e >> 6;
            int k4 = (e & 63) * 4;
            float4 v = __ldg(a4 + e);
            __nv_bfloat16 h0 = __float2bfloat16(v.x);
            __nv_bfloat16 h1 = __float2bfloat16(v.y);
            __nv_bfloat16 h2 = __float2bfloat16(v.z);
            __nv_bfloat16 h3 = __float2bfloat16(v.w);
            __nv_bfloat16 l0 = __float2bfloat16(v.x - __bfloat162float(h0));
            __nv_bfloat16 l1 = __float2bfloat16(v.y - __bfloat162float(h1));
            __nv_bfloat16 l2 = __float2bfloat16(v.z - __bfloat162float(h2));
            __nv_bfloat16 l3 = __float2bfloat16(v.w - __bfloat162float(h3));
            uint32_t off = (uint32_t)row * 544 + (uint32_t)k4 * 2;
            uint2 hv, lv;
            hv.x = ((uint32_t)__bfloat16_as_ushort(h1) << 16) | __bfloat16_as_ushort(h0);
            hv.y = ((uint32_t)__bfloat16_as_ushort(h3) << 16) | __bfloat16_as_ushort(h2);
            lv.x = ((uint32_t)__bfloat16_as_ushort(l1) << 16) | __bfloat16_as_ushort(l0);
            lv.y = ((uint32_t)__bfloat16_as_ushort(l3) << 16) | __bfloat16_as_ushort(l2);
            *(uint2*)(smem + SA_HI + off) = hv;
            *(uint2*)(smem + SA_LO + off) = lv;
        }
    }
    __syncthreads();

    const int m0 = wid * 16;                 // 8 warps cover m=128
    const int lr = lane & 15, lc = lane >> 4;
    const uint32_t a_off = sb + (uint32_t)(m0 + lr) * 544 + (uint32_t)lc * 16;
    const uint32_t b_base = (uint32_t)lr * 80;

    // A fragments resident: m16 x K256, hi+lo = 128 regs
    uint32_t Ah[16][4], Al[16][4];
    #pragma unroll
    for (int ks = 0; ks < 16; ks++) {
        LDSM_X4(Ah[ks], a_off + (uint32_t)ks * 32 + SA_HI);
        LDSM_X4(Al[ks], a_off + (uint32_t)ks * 32 + SA_LO);
    }

    const size_t row_base = (size_t)blockIdx.x * 128;

    for (int c = 0; c < nc; c++) {
        const int buf = c & 1;
        MBAR_WAIT(sb + SMB + buf * 8, (c >> 1) & 1);
        const uint32_t Bb = sb + SB + buf * (2 * CH_BYTES) + b_base;

        float acc[4][4];
        #pragma unroll
        for (int nf = 0; nf < 4; nf++)
            #pragma unroll
            for (int i = 0; i < 4; i++) acc[nf][i] = 0.0f;

        uint32_t bh[2][4][2], bl[2][4][2];
        #define GEMM_LOAD_B(B, KS) do { \
            _Pragma("unroll") \
            for (int nf = 0; nf < 4; nf++) { \
                uint32_t ba = Bb + (uint32_t)(KS) * (16 * 80) + (uint32_t)nf * 16; \
                LDSM_X2T(bh[B][nf], ba); \
                LDSM_X2T(bl[B][nf], ba + CH_BYTES); \
            } \
        } while (0)

        GEMM_LOAD_B(0, 0);
        #pragma unroll
        for (int ks = 0; ks < 16; ks++) {
            const int cur = ks & 1;
            if (ks < 15) GEMM_LOAD_B(cur ^ 1, ks + 1);
            #pragma unroll
            for (int nf = 0; nf < 4; nf++)
                MMA16816(acc[nf], Ah[ks], bh[cur][nf]);
            #pragma unroll
            for (int nf = 0; nf < 4; nf++)
                MMA16816(acc[nf], Al[ks], bh[cur][nf]);
            #pragma unroll
            for (int nf = 0; nf < 4; nf++)
                MMA16816(acc[nf], Ah[ks], bl[cur][nf]);
        }
        #undef GEMM_LOAD_B

        const float sc = (!which && c < 8) ? ATT_SCALE : 1.0f;
        const int colb = c * 32 + 2 * (lane & 3);
        const size_t r0 = row_base + m0 + (lane >> 2);
        #pragma unroll
        for (int nf = 0; nf < 4; nf++) {
            int cc = colb + nf * 8;
            float b0 = __ldg(bias + cc), b1 = __ldg(bias + cc + 1);
            float2 o0 = make_float2((acc[nf][0] + b0) * sc,
                                    (acc[nf][1] + b1) * sc);
            float2 o1 = make_float2((acc[nf][2] + b0) * sc,
                                    (acc[nf][3] + b1) * sc);
            *(float2*)(dst + r0 * dstride + cc) = o0;
            *(float2*)(dst + (r0 + 8) * dstride + cc) = o1;
        }
        __syncthreads();
        if (tid == 0 && c + 2 < nc) {
            uint32_t mb = sb + SMB + buf * 8;
            MBAR_EXPECT_TX(mb, 2 * CH_BYTES);
            uint32_t d = sb + SB + buf * (2 * CH_BYTES);
            BULK_G2S(d,            (const void*)(Whi + (c + 2) * CH_ELEMS), CH_BYTES, mb);
            BULK_G2S(d + CH_BYTES, (const void*)(Wlo + (c + 2) * CH_ELEMS), CH_BYTES, mb);
        }
    }
}

// ---------------- kernel 3: attention via HMMA ----------------
#define AH_BYTES 27648
#define AKT_OFF  10240
#define AV_OFF   17408
#define ATT_SMEM (8 * AH_BYTES)          // 221184

__global__ __launch_bounds__(256, 1)
void attn_hmma(int nW) {
    extern __shared__ __align__(128) char am[];
    const uint32_t sb = smem_u32(am);
    const int tid = threadIdx.x, wid = tid >> 5, lane = tid & 31;
    const int lr = lane & 15, lc = lane >> 4;
    const int rr = lane >> 2, c2 = 2 * (lane & 3);
    const int b = blockIdx.x;
    const size_t base = (size_t)b * NTOK;
    const float* qkvw = g_qkv + base * 768;

    // ---- cooperative load of all 8 head slots ----
    #pragma unroll 1
    for (int s = 0; s < 8; s++) {
        char* hq = am + s * AH_BYTES;
        const float* qsrc = qkvw + s * HD;
        #pragma unroll
        for (int it = 0; it < 8; it++) {            // q & v: 64x32 (pad rows 0)
            int i = it * 256 + tid;
            int m = i >> 5, d = i & 31;
            float qv = 0.0f, vv = 0.0f;
            if (m < NTOK) {
                qv = __ldg(qsrc + (size_t)m * 768 + d);
                vv = __ldg(qsrc + 512 + (size_t)m * 768 + d);
            }
            __nv_bfloat16 qh = __float2bfloat16(qv);
            __nv_bfloat16 ql = __float2bfloat16(qv - __bfloat162float(qh));
            __nv_bfloat16 vh = __float2bfloat16(vv);
            __nv_bfloat16 vl = __float2bfloat16(vv - __bfloat162float(vh));
            int off = m * 80 + d * 2;
            *(__nv_bfloat16*)(hq + off) = qh;
            *(__nv_bfloat16*)(hq + 5120 + off) = ql;
            *(__nv_bfloat16*)(hq + AV_OFF + off) = vh;
            *(__nv_bfloat16*)(hq + AV_OFF + 5120 + off) = vl;
        }
        #pragma unroll
        for (int it = 0; it < 7; it++) {            // kT: [d][tok], 49 + 7 pad
            int i = it * 256 + tid;
            int m = i >> 5, d = i & 31;
            if (m < 56) {
                float kv = (m < NTOK)
                    ? __ldg(qsrc + 256 + (size_t)m * 768 + d) : 0.0f;
                __nv_bfloat16 kh = __float2bfloat16(kv);
                __nv_bfloat16 kl = __float2bfloat16(kv - __bfloat162float(kh));
                int off = (d * 56 + m) * 2;
                *(__nv_bfloat16*)(hq + AKT_OFF + off) = kh;
                *(__nv_bfloat16*)(hq + AKT_OFF + 3584 + off) = kl;
            }
        }
    }
    __syncthreads();

    const uint32_t hb = sb + wid * AH_BYTES;

    // ---- S = Q * K^T  (M=64, N=56, K=32, 3-term split, pipelined A) ----
    float acc[4][7][4];
    #pragma unroll
    for (int mf = 0; mf < 4; mf++)
        #pragma unroll
        for (int nf = 0; nf < 7; nf++)
            #pragma unroll
            for (int i = 0; i < 4; i++) acc[mf][nf][i] = 0.0f;

    #pragma unroll
    for (int kk = 0; kk < 2; kk++) {
        uint32_t kfh[7][2], kfl[7][2];
        #pragma unroll
        for (int nf = 0; nf < 7; nf++) {
            uint32_t ba = hb + AKT_OFF + (uint32_t)(kk * 16 + lr) * 112
                        + (uint32_t)nf * 16;
            LDSM_X2T(kfh[nf], ba);
            LDSM_X2T(kfl[nf], ba + 3584);
        }
        uint32_t ah[2][4], al[2][4];
        {
            uint32_t aa0 = hb + (uint32_t)lr * 80 + (uint32_t)(kk * 32)
                         + (uint32_t)lc * 16;
            LDSM_X4(ah[0], aa0);
            LDSM_X4(al[0], aa0 + 5120);
        }
        #pragma unroll
        for (int mf = 0; mf < 4; mf++) {
            const int cur = mf & 1;
            if (mf < 3) {
                uint32_t aa = hb + (uint32_t)((mf + 1) * 16 + lr) * 80
                            + (uint32_t)(kk * 32) + (uint32_t)lc * 16;
                LDSM_X4(ah[cur ^ 1], aa);
                LDSM_X4(al[cur ^ 1], aa + 5120);
            }
            #pragma unroll
            for (int nf = 0; nf < 7; nf++) MMA16816(acc[mf][nf], ah[cur], kfh[nf]);
            #pragma unroll
            for (int nf = 0; nf < 7; nf++) MMA16816(acc[mf][nf], al[cur], kfh[nf]);
            #pragma unroll
            for (int nf = 0; nf < 7; nf++) MMA16816(acc[mf][nf], ah[cur], kfl[nf]);
        }
    }

    // ---- V fragments hoisted: loaded once, reused over all 4 mf ----
    uint32_t vh[4][4][2], vl[4][4][2];
    #pragma unroll
    for (int kk = 0; kk < 4; kk++)
        #pragma unroll
        for (int nf = 0; nf < 4; nf++) {
            uint32_t ba = hb + AV_OFF + (uint32_t)(kk * 16 + lr) * 80
                        + (uint32_t)nf * 16;
            LDSM_X2T(vh[kk][nf], ba);
            LDSM_X2T(vl[kk][nf], ba + 5120);
        }

    const float* bmf = g_bm + ((size_t)(b % nW) * NH + wid) * BMF_PER_WH;
    float* og = g_attn + base * 256 + wid * HD;

    // ---- per mf: bias, softmax in fragments, pack P, P*V, store ----
    #pragma unroll
    for (int mf = 0; mf < 4; mf++) {
        #pragma unroll
        for (int nf = 0; nf < 7; nf++) {
            const float* bp = bmf + ((mf * 7 + nf) * 4) * 32 + lane;
            acc[mf][nf][0] += __ldg(bp);
            acc[mf][nf][1] += __ldg(bp + 32);
            acc[mf][nf][2] += __ldg(bp + 64);
            acc[mf][nf][3] += __ldg(bp + 96);
        }
        float m1 = -1e30f, m2 = -1e30f;
        #pragma unroll
        for (int nf = 0; nf < 7; nf++) {
            m1 = fmaxf(m1, fmaxf(acc[mf][nf][0], acc[mf][nf][1]));
            m2 = fmaxf(m2, fmaxf(acc[mf][nf][2], acc[mf][nf][3]));
        }
        m1 = fmaxf(m1, __shfl_xor_sync(0xffffffffu, m1, 1));
        m1 = fmaxf(m1, __shfl_xor_sync(0xffffffffu, m1, 2));
        m2 = fmaxf(m2, __shfl_xor_sync(0xffffffffu, m2, 1));
        m2 = fmaxf(m2, __shfl_xor_sync(0xffffffffu, m2, 2));
        float s1 = 0.0f, s2 = 0.0f;
        #pragma unroll
        for (int nf = 0; nf < 7; nf++) {
            acc[mf][nf][0] = __expf(acc[mf][nf][0] - m1);
            acc[mf][nf][1] = __expf(acc[mf][nf][1] - m1);
            acc[mf][nf][2] = __expf(acc[mf][nf][2] - m2);
            acc[mf][nf][3] = __expf(acc[mf][nf][3] - m2);
            s1 += acc[mf][nf][0] + acc[mf][nf][1];
            s2 += acc[mf][nf][2] + acc[mf][nf][3];
        }
        s1 += __shfl_xor_sync(0xffffffffu, s1, 1);
        s1 += __shfl_xor_sync(0xffffffffu, s1, 2);
        s2 += __shfl_xor_sync(0xffffffffu, s2, 1);
        s2 += __shfl_xor_sync(0xffffffffu, s2, 2);
        const float inv1 = 1.0f / s1, inv2 = 1.0f / s2;

        // O = P * V (K=64 via 4 k16 blocks; V fragments from registers)
        float o[4][4];
        #pragma unroll
        for (int nf = 0; nf < 4; nf++)
            #pragma unroll
            for (int i = 0; i < 4; i++) o[nf][i] = 0.0f;

        #pragma unroll
        for (int kk = 0; kk < 4; kk++) {
            uint32_t ph[4], pl[4];
            sp2(acc[mf][2 * kk][0], acc[mf][2 * kk][1], ph[0], pl[0]);
            sp2(acc[mf][2 * kk][2], acc[mf][2 * kk][3], ph[1], pl[1]);
            if (kk < 3) {
                sp2(acc[mf][2 * kk + 1][0], acc[mf][2 * kk + 1][1], ph[2], pl[2]);
                sp2(acc[mf][2 * kk + 1][2], acc[mf][2 * kk + 1][3], ph[3], pl[3]);
            } else {
                ph[2] = 0u; pl[2] = 0u; ph[3] = 0u; pl[3] = 0u;
            }
            #pragma unroll
            for (int nf = 0; nf < 4; nf++) MMA16816(o[nf], ph, vh[kk][nf]);
            #pragma unroll
            for (int nf = 0; nf < 4; nf++) MMA16816(o[nf], pl, vh[kk][nf]);
            #pragma unroll
            for (int nf = 0; nf < 4; nf++) MMA16816(o[nf], ph, vl[kk][nf]);
        }

        const int r1 = mf * 16 + rr, r2 = r1 + 8;
        #pragma unroll
        for (int nf = 0; nf < 4; nf++) {
            if (r1 < NTOK) {
                float2 v0 = make_float2(o[nf][0] * inv1, o[nf][1] * inv1);
                *(float2*)(og + (size_t)r1 * 256 + nf * 8 + c2) = v0;
            }
            if (r2 < NTOK) {
                float2 v1 = make_float2(o[nf][2] * inv2, o[nf][3] * inv2);
                *(float2*)(og + (size_t)r2 * 256 + nf * 8 + c2) = v1;
            }
        }
    }
}

// ---------------- launch ----------------
extern "C" void kernel_launch(void* const* d_in, const int* in_sizes, int n_in,
                              void* d_out, int out_size) {
    const float* x          = (const float*)d_in[0];
    const float* mask       = (const float*)d_in[1];
    const float* qkv_w      = (const float*)d_in[2];
    const float* qkv_b      = (const float*)d_in[3];
    const float* proj_w     = (const float*)d_in[4];
    const float* proj_b     = (const float*)d_in[5];
    const float* bias_table = (const float*)d_in[6];
    const int*   rel_index  = (const int*)d_in[7];
    float* out = (float*)d_out;

    const int nW = in_sizes[1] / (NTOK * NTOK);     // 64

    cudaFuncSetAttribute(gemm_hmma,
                         cudaFuncAttributeMaxDynamicSharedMemorySize, GEMM_SMEM);
    cudaFuncSetAttribute(attn_hmma,
                         cudaFuncAttributeMaxDynamicSharedMemorySize, ATT_SMEM);

    prep_weights<<<QKV_NC + PROJ_NC + 72, 256>>>(qkv_w, proj_w, mask,
                                                 bias_table, rel_index, nW);
    gemm_hmma<<<NTILES, 256, GEMM_SMEM>>>(x, qkv_b, nullptr, 0);
    attn_hmma<<<2048, 256, ATT_SMEM>>>(nW);
    gemm_hmma<<<NTILES, 256, GEMM_SMEM>>>(nullptr, proj_b, out, 1);
}